// round 2
// baseline (speedup 1.0000x reference)
#include <cuda_runtime.h>
#include <math.h>

typedef unsigned long long u64;

#define TOKENS 1024
#define CDIM   512
#define QKVD   1536
#define NSEQ   256
#define HEADS  8
#define DH     64
#define QT     32
#define KT     64
#define EPSF   1e-6f
#define T_SMALL 0.009f

// ---------------- packed f32x2 helpers ----------------
__device__ __forceinline__ u64 pk2(float lo, float hi) {
    u64 r; asm("mov.b64 %0,{%1,%2};" : "=l"(r) : "f"(lo), "f"(hi)); return r;
}
__device__ __forceinline__ void up2(u64 v, float& lo, float& hi) {
    asm("mov.b64 {%0,%1},%2;" : "=f"(lo), "=f"(hi) : "l"(v));
}
__device__ __forceinline__ u64 fadd2(u64 a, u64 b) {
    u64 r; asm("add.rn.f32x2 %0,%1,%2;" : "=l"(r) : "l"(a), "l"(b)); return r;
}
__device__ __forceinline__ u64 fmul2(u64 a, u64 b) {
    u64 r; asm("mul.rn.f32x2 %0,%1,%2;" : "=l"(r) : "l"(a), "l"(b)); return r;
}
__device__ __forceinline__ u64 ffma2(u64 a, u64 b, u64 c) {
    u64 r; asm("fma.rn.f32x2 %0,%1,%2,%3;" : "=l"(r) : "l"(a), "l"(b), "l"(c)); return r;
}

// ---------------- device scratch (no allocs allowed) ----------------
__device__ float g_qkv[TOKENS * QKVD];
__device__ float g_att[TOKENS * CDIM];
__device__ float g_qs [TOKENS * CDIM];
__device__ float g_qc [TOKENS * CDIM];
__device__ float g_knv[TOKENS * CDIM];   // -k
__device__ float g_kns[TOKENS * CDIM];   // -sin(R k)
__device__ float g_kc [TOKENS * CDIM];   //  cos(R k)

// ---------------------------------------------------------------------------
// Trig precompute: one pass over q and k halves of qkv. Coalesced in and out.
// ---------------------------------------------------------------------------
__global__ __launch_bounds__(256)
void trig_prep(const float* __restrict__ qkv, const float* __restrict__ paramR,
               float* __restrict__ gqs, float* __restrict__ gqc,
               float* __restrict__ gknv, float* __restrict__ gkns,
               float* __restrict__ gkc)
{
    int i = blockIdx.x * 256 + threadIdx.x;           // < TOKENS*CDIM
    const float R = paramR[0];
    int tok = i >> 9, col = i & 511;
    float qv = qkv[tok * QKVD + col];
    float s, c;
    sincosf(R * qv, &s, &c);
    gqs[i] = s; gqc[i] = c;
    float kv = qkv[tok * QKVD + CDIM + col];
    sincosf(R * kv, &s, &c);
    gknv[i] = -kv; gkns[i] = -s; gkc[i] = c;
}

// ---------------------------------------------------------------------------
// f32x2 SGEMM: C[M,Ncols] = A[M,K] * Bw[Ncols,K]^T (+bias)
// Tile BM x 64, BK=16, per-thread 8(M, as 4 f32x2 pairs) x 4(N). NT = 2*BM.
// Accumulators packed over M-pairs; B stored duplicated {b,b} in smem.
// ---------------------------------------------------------------------------
template<int BM, int NT>
__global__ __launch_bounds__(NT)
void sgemm2(const float* __restrict__ A, const float* __restrict__ Bw,
            const float* __restrict__ bias, float* __restrict__ C,
            int Ncols, int K)
{
    __shared__ __align__(16) float  As[16][BM];
    __shared__ __align__(16) float2 Bs[16][64];
    const int t  = threadIdx.x;
    const int m0 = blockIdx.y * BM;
    const int n0 = blockIdx.x * 64;
    const int tx = t & 15, ty = t >> 4;
    const int m8 = ty * 8, n4 = tx * 4;
    constexpr int BF4 = 256 / NT;      // float4 B loads per thread (1 or 2)

    u64 acc[4][4];
    #pragma unroll
    for (int i = 0; i < 4; i++)
        #pragma unroll
        for (int j = 0; j < 4; j++) acc[i][j] = pk2(0.f, 0.f);

    float4 pa[2], pb[BF4];
    const int nit = K / 16;

    // preload iter 0
    #pragma unroll
    for (int v = 0; v < 2; v++) {
        int f4 = t + v * NT; int m = f4 >> 2, kq = (f4 & 3) << 2;
        pa[v] = *(const float4*)&A[(m0 + m) * K + kq];
    }
    #pragma unroll
    for (int v = 0; v < BF4; v++) {
        int f4 = t + v * NT; int n = f4 >> 2, kq = (f4 & 3) << 2;
        pb[v] = *(const float4*)&Bw[(n0 + n) * K + kq];
    }

    for (int it = 0; it < nit; ++it) {
        // regs -> smem
        #pragma unroll
        for (int v = 0; v < 2; v++) {
            int f4 = t + v * NT; int m = f4 >> 2, kq = (f4 & 3) << 2;
            As[kq+0][m] = pa[v].x; As[kq+1][m] = pa[v].y;
            As[kq+2][m] = pa[v].z; As[kq+3][m] = pa[v].w;
        }
        #pragma unroll
        for (int v = 0; v < BF4; v++) {
            int f4 = t + v * NT; int n = f4 >> 2, kq = (f4 & 3) << 2;
            Bs[kq+0][n] = make_float2(pb[v].x, pb[v].x);
            Bs[kq+1][n] = make_float2(pb[v].y, pb[v].y);
            Bs[kq+2][n] = make_float2(pb[v].z, pb[v].z);
            Bs[kq+3][n] = make_float2(pb[v].w, pb[v].w);
        }
        __syncthreads();
        if (it + 1 < nit) {
            int k0 = (it + 1) * 16;
            #pragma unroll
            for (int v = 0; v < 2; v++) {
                int f4 = t + v * NT; int m = f4 >> 2, kq = (f4 & 3) << 2;
                pa[v] = *(const float4*)&A[(m0 + m) * K + k0 + kq];
            }
            #pragma unroll
            for (int v = 0; v < BF4; v++) {
                int f4 = t + v * NT; int n = f4 >> 2, kq = (f4 & 3) << 2;
                pb[v] = *(const float4*)&Bw[(n0 + n) * K + k0 + kq];
            }
        }
        #pragma unroll
        for (int k = 0; k < 16; ++k) {
            float4 a01 = *(const float4*)&As[k][m8];
            float4 a23 = *(const float4*)&As[k][m8 + 4];
            float4 b01 = *(const float4*)&Bs[k][n4];
            float4 b23 = *(const float4*)&Bs[k][n4 + 2];
            u64 a2[4] = { pk2(a01.x, a01.y), pk2(a01.z, a01.w),
                          pk2(a23.x, a23.y), pk2(a23.z, a23.w) };
            u64 b2[4] = { pk2(b01.x, b01.y), pk2(b01.z, b01.w),
                          pk2(b23.x, b23.y), pk2(b23.z, b23.w) };
            #pragma unroll
            for (int mp = 0; mp < 4; mp++)
                #pragma unroll
                for (int nn = 0; nn < 4; nn++)
                    acc[mp][nn] = ffma2(a2[mp], b2[nn], acc[mp][nn]);
        }
        __syncthreads();
    }

    float bb0 = 0.f, bb1 = 0.f, bb2 = 0.f, bb3 = 0.f;
    if (bias) {
        float4 bv = *(const float4*)&bias[n0 + n4];
        bb0 = bv.x; bb1 = bv.y; bb2 = bv.z; bb3 = bv.w;
    }
    #pragma unroll
    for (int mp = 0; mp < 4; mp++) {
        int r0 = m0 + m8 + 2 * mp;
        float lo0, hi0, lo1, hi1, lo2, hi2, lo3, hi3;
        up2(acc[mp][0], lo0, hi0); up2(acc[mp][1], lo1, hi1);
        up2(acc[mp][2], lo2, hi2); up2(acc[mp][3], lo3, hi3);
        float4 o0 = make_float4(lo0 + bb0, lo1 + bb1, lo2 + bb2, lo3 + bb3);
        float4 o1 = make_float4(hi0 + bb0, hi1 + bb1, hi2 + bb2, hi3 + bb3);
        *(float4*)&C[(size_t)r0 * Ncols + n0 + n4]       = o0;
        *(float4*)&C[(size_t)(r0 + 1) * Ncols + n0 + n4] = o1;
    }
}

// ---------------------------------------------------------------------------
// Fourier attention, f32x2 packed over dim-pairs. Block = (qtile, head, batch).
// 256 threads: lane q = tid&31 (query), kg = tid>>5 picks 8 keys per k-tile.
// ---------------------------------------------------------------------------
#define PADQ 66
static const int ATTN_SMEM = (3 * QT * PADQ + 3 * KT * DH + NSEQ * QT + 8 * QT + QT) * 4;

__global__ __launch_bounds__(256, 2)
void fourier_attn2(const float* __restrict__ qkv,
                   const float* __restrict__ gqs, const float* __restrict__ gqc,
                   const float* __restrict__ gknv, const float* __restrict__ gkns,
                   const float* __restrict__ gkc,
                   const float* __restrict__ paramR, float* __restrict__ attout)
{
    extern __shared__ float sm[];
    float* sQv = sm;                     // [32][66]
    float* sQs = sQv + QT * PADQ;
    float* sQc = sQs + QT * PADQ;
    float* sKv = sQc + QT * PADQ;        // [64][64]
    float* sKs = sKv + KT * DH;
    float* sKc = sKs + KT * DH;
    float* sS  = sKc + KT * DH;          // [256][32]
    float* sRed = sS + NSEQ * QT;        // [8][32]
    float* sInv = sRed + 8 * QT;         // [32]

    const int tid = threadIdx.x;
    const int q = tid & 31, kg = tid >> 5;
    const int qt = blockIdx.x, h = blockIdx.y, b = blockIdx.z;
    const int tok0 = b * NSEQ, q0 = qt * QT;
    const float R = paramR[0];

    // ---- q-side fill (float2 copies from precomputed trig) ----
    for (int i = tid; i < QT * 32; i += 256) {       // 32 float2 per row
        int qq = i >> 5, d2 = i & 31;
        int g = (tok0 + q0 + qq) * CDIM + h * DH + d2 * 2;
        int sidx = qq * PADQ + d2 * 2;
        *(float2*)&sQs[sidx] = *(const float2*)&gqs[g];
        *(float2*)&sQc[sidx] = *(const float2*)&gqc[g];
        *(float2*)&sQv[sidx] = *(const float2*)&qkv[(tok0 + q0 + qq) * QKVD + h * DH + d2 * 2];
    }

    for (int kc0 = 0; kc0 < NSEQ; kc0 += KT) {
        __syncthreads();
        for (int i = tid; i < KT * 16; i += 256) {   // 16 float4 per key row
            int kk = i >> 4, dq = (i & 15) * 4;
            int g = (tok0 + kc0 + kk) * CDIM + h * DH + dq;
            int sidx = kk * DH + dq;
            *(float4*)&sKv[sidx] = *(const float4*)&gknv[g];
            *(float4*)&sKs[sidx] = *(const float4*)&gkns[g];
            *(float4*)&sKc[sidx] = *(const float4*)&gkc[g];
        }
        __syncthreads();

        u64 np[8], dp[8];
        #pragma unroll
        for (int j = 0; j < 8; j++) { np[j] = pk2(1.f, 1.f); dp[j] = pk2(1.f, 1.f); }
        const int kb0 = kg * 8 * DH;

        #pragma unroll 4
        for (int d2 = 0; d2 < 32; d2++) {
            u64 qv2 = *(const u64*)&sQv[q * PADQ + d2 * 2];
            u64 qs2 = *(const u64*)&sQs[q * PADQ + d2 * 2];
            u64 qc2 = *(const u64*)&sQc[q * PADQ + d2 * 2];
            #pragma unroll
            for (int j = 0; j < 8; j++) {
                int kidx = kb0 + j * DH + d2 * 2;
                u64 kv2 = *(const u64*)&sKv[kidx];
                u64 ks2 = *(const u64*)&sKs[kidx];
                u64 kc2 = *(const u64*)&sKc[kidx];
                u64 diff2 = fadd2(qv2, kv2);                       // q - k
                u64 num2  = ffma2(qs2, kc2, fmul2(qc2, ks2));      // sin(R(q-k))
                float d0, d1, n0, n1;
                up2(diff2, d0, d1); up2(num2, n0, n1);
                bool s0 = fabsf(d0) < T_SMALL, s1 = fabsf(d1) < T_SMALL;
                float na = s0 ? R : n0,  nb = s1 ? R : n1;
                float da = s0 ? 1.f : d0, db = s1 ? 1.f : d1;
                np[j] = fmul2(np[j], pk2(na, nb));
                dp[j] = fmul2(dp[j], pk2(da, db));
            }
        }
        #pragma unroll
        for (int j = 0; j < 8; j++) {
            float na, nb, da, db;
            up2(np[j], na, nb); up2(dp[j], da, db);
            float npp = na * nb, dpp = da * db;
            float s = (dpp != 0.f) ? npp / dpp : 0.f;
            float s2 = s * s;
            sS[(kc0 + kg * 8 + j) * QT + q] = s2 * s2;
        }
    }
    __syncthreads();

    // ---- row sums ----
    {
        float part = 0.f;
        #pragma unroll 8
        for (int j = kg * 32; j < kg * 32 + 32; j++) part += sS[j * QT + q];
        sRed[kg * QT + q] = part;
    }
    __syncthreads();
    if (kg == 0) {
        float ss = 0.f;
        #pragma unroll
        for (int r = 0; r < 8; r++) ss += sRed[r * QT + q];
        sInv[q] = 1.f / (ss + EPSF);
    }

    // ---- PV (packed over dim pairs) ----
    u64 acc[4];
    #pragma unroll
    for (int i = 0; i < 4; i++) acc[i] = pk2(0.f, 0.f);
    for (int kc0 = 0; kc0 < NSEQ; kc0 += KT) {
        __syncthreads();
        for (int i = tid; i < KT * 16; i += 256) {
            int kk = i >> 4, dq = (i & 15) * 4;
            *(float4*)&sKv[kk * DH + dq] =
                *(const float4*)&qkv[(tok0 + kc0 + kk) * QKVD + 2 * CDIM + h * DH + dq];
        }
        __syncthreads();
        #pragma unroll 4
        for (int jj = 0; jj < KT; jj++) {
            float a = sS[(kc0 + jj) * QT + q];
            u64 a2 = pk2(a, a);
            const float* vp = &sKv[jj * DH + kg * 8];
            float4 v0 = *(const float4*)vp;
            float4 v1 = *(const float4*)(vp + 4);
            acc[0] = ffma2(a2, pk2(v0.x, v0.y), acc[0]);
            acc[1] = ffma2(a2, pk2(v0.z, v0.w), acc[1]);
            acc[2] = ffma2(a2, pk2(v1.x, v1.y), acc[2]);
            acc[3] = ffma2(a2, pk2(v1.z, v1.w), acc[3]);
        }
    }
    float rinv = sInv[q];
    float o[8];
    up2(acc[0], o[0], o[1]); up2(acc[1], o[2], o[3]);
    up2(acc[2], o[4], o[5]); up2(acc[3], o[6], o[7]);
    float4 w0 = make_float4(o[0] * rinv, o[1] * rinv, o[2] * rinv, o[3] * rinv);
    float4 w1 = make_float4(o[4] * rinv, o[5] * rinv, o[6] * rinv, o[7] * rinv);
    float* dst = &attout[(tok0 + q0 + q) * CDIM + h * DH + kg * 8];
    *(float4*)dst       = w0;
    *(float4*)(dst + 4) = w1;
}

extern "C" void kernel_launch(void* const* d_in, const int* in_sizes, int n_in,
                              void* d_out, int out_size)
{
    const float* x      = (const float*)d_in[0];
    const float* w_qkv  = (const float*)d_in[1];
    const float* w_proj = (const float*)d_in[2];
    const float* b_proj = (const float*)d_in[3];
    const float* paramR = (const float*)d_in[4];
    float* out = (float*)d_out;

    float *qkvbuf, *attbuf, *gqs, *gqc, *gknv, *gkns, *gkc;
    cudaGetSymbolAddress((void**)&qkvbuf, g_qkv);
    cudaGetSymbolAddress((void**)&attbuf, g_att);
    cudaGetSymbolAddress((void**)&gqs,  g_qs);
    cudaGetSymbolAddress((void**)&gqc,  g_qc);
    cudaGetSymbolAddress((void**)&gknv, g_knv);
    cudaGetSymbolAddress((void**)&gkns, g_kns);
    cudaGetSymbolAddress((void**)&gkc,  g_kc);

    cudaFuncSetAttribute(fourier_attn2, cudaFuncAttributeMaxDynamicSharedMemorySize,
                         ATTN_SMEM);

    // 1) qkv = x @ w_qkv^T   (1024 x 1536, K=512)
    sgemm2<128, 256><<<dim3(QKVD / 64, TOKENS / 128), 256>>>(x, w_qkv, nullptr,
                                                             qkvbuf, QKVD, CDIM);
    // 2) trig precompute over q,k halves
    trig_prep<<<TOKENS * CDIM / 256, 256>>>(qkvbuf, paramR, gqs, gqc, gknv, gkns, gkc);
    // 3) attention core
    fourier_attn2<<<dim3(NSEQ / QT, HEADS, 4), 256, ATTN_SMEM>>>(
        qkvbuf, gqs, gqc, gknv, gkns, gkc, paramR, attbuf);
    // 4) out = att @ w_proj^T + b_proj
    sgemm2<64, 128><<<dim3(CDIM / 64, TOKENS / 64), 128>>>(attbuf, w_proj, b_proj,
                                                           out, CDIM, CDIM);
}